// round 3
// baseline (speedup 1.0000x reference)
#include <cuda_runtime.h>
#include <stdint.h>

// RGCN layer: out = relu( scatter_add_dst( x[src] @ W_rel[edge_type] ) + x @ W_self + bias )
//
//   1. detect edge dtype (int32 vs int64) on device (JAX downgrades int64->int32
//      unless x64 is enabled, so we must not assume).
//   2. counting-sort edges by relation into padded 128-aligned segments,
//      appending N synthetic self-edges as relation R (weights = W_self).
//   3. init out = bias
//   4. gather-GEMM over all segments: TM=128 edges x TN=64 cols, K-chunks of 32;
//      epilogue = red.global.add.v4.f32 into out[dst].
//   5. relu in place.
//
// Inputs are bound BY ELEMENT COUNT (all six pairwise distinct).

#define D   256
#define TM  128
#define TN  64
#define TK  32
#define RMAX 32
#define MAXSEG 1200000   // >= E + N + (R+1)*TM padding

__device__ int g_cnt[RMAX + 1];
__device__ int g_cur[RMAX + 1];
__device__ int g_off[RMAX + 2];
__device__ int g_srcbuf[MAXSEG];
__device__ int g_dstbuf[MAXSEG];
__device__ int g_ntiles;
__device__ int g_is64;

// ---------------------------------------------------------------------------
// dtype probe: int64 node ids < 2^32 have high word == 0 (little-endian);
// int32 data has a random id there (≈never 0). Majority vote over 256 pairs.
__global__ void k_detect(const int2* __restrict__ ei_pairs, int npairs) {
    __shared__ int zcnt;
    if (threadIdx.x == 0) zcnt = 0;
    __syncthreads();
    int i = threadIdx.x;
    if (i < npairs && ei_pairs[i].y == 0) atomicAdd(&zcnt, 1);
    __syncthreads();
    if (threadIdx.x == 0) g_is64 = (zcnt > npairs / 2) ? 1 : 0;
}

__global__ void k_zero_cnt(int R) {
    int i = threadIdx.x;
    if (i <= R) g_cnt[i] = 0;
}

__global__ void k_hist(const void* __restrict__ et, int E, int R) {
    __shared__ int h[RMAX + 1];
    if (threadIdx.x <= R) h[threadIdx.x] = 0;
    __syncthreads();
    int i = blockIdx.x * blockDim.x + threadIdx.x;
    if (i < E) {
        int r = g_is64 ? (int)((const long long*)et)[i] : ((const int*)et)[i];
        if (r < 0) r = 0;
        if (r >= R) r = R - 1;
        atomicAdd(&h[r], 1);
    }
    __syncthreads();
    if (threadIdx.x <= R && h[threadIdx.x]) atomicAdd(&g_cnt[threadIdx.x], h[threadIdx.x]);
}

// single-thread scan: padded (TM-aligned) segment offsets; relation R = self edges
__global__ void k_scan(int R, int N) {
    g_cnt[R] = N;
    int off = 0;
    for (int r = 0; r <= R; r++) {
        g_off[r] = off;
        g_cur[r] = off;
        off += ((g_cnt[r] + TM - 1) / TM) * TM;
    }
    g_off[R + 1] = off;
    g_ntiles = off / TM;
}

__global__ void k_scatter(const void* __restrict__ ei,
                          const void* __restrict__ et,
                          int E, int N, int R) {
    int i = blockIdx.x * blockDim.x + threadIdx.x;
    int is64 = g_is64;
    if (i < E) {
        int r, s, d;
        if (is64) {
            r = (int)((const long long*)et)[i];
            s = (int)((const long long*)ei)[i];
            d = (int)((const long long*)ei)[E + i];
        } else {
            r = ((const int*)et)[i];
            s = ((const int*)ei)[i];
            d = ((const int*)ei)[E + i];
        }
        if (r < 0) r = 0;
        if (r >= R) r = R - 1;
        if (s < 0 || s >= N) s = 0;
        if (d < 0 || d >= N) d = 0;
        int p = atomicAdd(&g_cur[r], 1);
        g_srcbuf[p] = s;
        g_dstbuf[p] = d;
    } else if (i < E + N) {
        int n = i - E;
        int p = g_off[R] + n;        // self edges, already "sorted"
        g_srcbuf[p] = n;
        g_dstbuf[p] = n;
    }
}

// mark padding rows (between cnt and aligned segment end) as invalid
__global__ void k_pad(int R) {
    int i = blockIdx.x * blockDim.x + threadIdx.x;
    int r = i / TM;
    int j = i % TM;
    if (r > R) return;
    int idx = g_off[r] + g_cnt[r] + j;
    if (idx < g_off[r + 1]) {
        g_srcbuf[idx] = -1;
        g_dstbuf[idx] = 0;
    }
}

__global__ void k_init(float* __restrict__ out, const float* __restrict__ bias, int total) {
    int i = blockIdx.x * blockDim.x + threadIdx.x;
    if (i < total) out[i] = bias[i & (D - 1)];
}

__global__ void k_relu(float* __restrict__ out, int total) {
    int i = blockIdx.x * blockDim.x + threadIdx.x;
    if (i < total) out[i] = fmaxf(out[i], 0.0f);
}

// ---------------------------------------------------------------------------
// gather-GEMM with atomic scatter epilogue.
// grid: (tiles_max, D/TN); block: 256 threads; each thread: 8x4 microtile.
__global__ __launch_bounds__(256) void k_gemm(
    const float* __restrict__ x,
    const float* __restrict__ W_rel,
    const float* __restrict__ W_self,
    float* __restrict__ out,
    int R)
{
    int t = blockIdx.x;
    if (t >= g_ntiles) return;
    int row0 = t * TM;

    // which relation segment does this tile live in?
    int rel = 0;
    while (g_off[rel + 1] <= row0) rel++;
    const float* __restrict__ W = (rel == R) ? W_self : (W_rel + (size_t)rel * D * D);

    int n0 = blockIdx.y * TN;
    int tid = threadIdx.x;
    int ty = tid >> 4;       // 0..15 -> rows ty*8 .. ty*8+7
    int tx = tid & 15;       // 0..15 -> cols tx*4 .. tx*4+3

    __shared__ int   s_src[TM];
    __shared__ int   s_dst[TM];
    __shared__ float As[TK][TM + 4];   // k-major; stride 132 floats (16B aligned)
    __shared__ float Bs[TK][TN + 4];   // stride 68 floats (16B aligned)

    if (tid < TM) {
        s_src[tid] = g_srcbuf[row0 + tid];
        s_dst[tid] = g_dstbuf[row0 + tid];
    }
    __syncthreads();

    float acc[8][4];
    #pragma unroll
    for (int i = 0; i < 8; i++)
        #pragma unroll
        for (int j = 0; j < 4; j++) acc[i][j] = 0.0f;

    #pragma unroll 1
    for (int kt = 0; kt < D / TK; kt++) {
        // load A tile (gathered): TM*TK = 4096 elems, 16 per thread
        #pragma unroll
        for (int i = 0; i < (TM * TK) / 256; i++) {
            int idx = tid + i * 256;
            int r = idx >> 5;           // /TK
            int k = idx & 31;           // %TK
            int sr = s_src[r];
            As[k][r] = (sr < 0) ? 0.0f : x[(size_t)sr * D + kt * TK + k];
        }
        // load B tile: TK*TN = 2048 elems, 8 per thread, coalesced 64-float rows
        #pragma unroll
        for (int i = 0; i < (TK * TN) / 256; i++) {
            int idx = tid + i * 256;
            int k = idx >> 6;           // /TN
            int n = idx & 63;           // %TN
            Bs[k][n] = W[(size_t)(kt * TK + k) * D + n0 + n];
        }
        __syncthreads();

        #pragma unroll
        for (int k = 0; k < TK; k++) {
            float4 a0 = *(const float4*)&As[k][ty * 8];
            float4 a1 = *(const float4*)&As[k][ty * 8 + 4];
            float4 b  = *(const float4*)&Bs[k][tx * 4];
            float av[8] = {a0.x, a0.y, a0.z, a0.w, a1.x, a1.y, a1.z, a1.w};
            float bv[4] = {b.x, b.y, b.z, b.w};
            #pragma unroll
            for (int i = 0; i < 8; i++)
                #pragma unroll
                for (int j = 0; j < 4; j++)
                    acc[i][j] = fmaf(av[i], bv[j], acc[i][j]);
        }
        __syncthreads();
    }

    // epilogue: vectorized reduction into out[dst]
    #pragma unroll
    for (int i = 0; i < 8; i++) {
        int r = ty * 8 + i;
        if (s_src[r] < 0) continue;
        float* p = out + (size_t)s_dst[r] * D + n0 + tx * 4;
        asm volatile("red.global.add.v4.f32 [%0], {%1, %2, %3, %4};"
                     :: "l"(p), "f"(acc[i][0]), "f"(acc[i][1]),
                        "f"(acc[i][2]), "f"(acc[i][3])
                     : "memory");
    }
}

// ---------------------------------------------------------------------------
extern "C" void kernel_launch(void* const* d_in, const int* in_sizes, int n_in,
                              void* d_out, int out_size) {
    // Bind inputs by element count (all six pairwise distinct):
    //   bias(256) < W_self(65,536) < edge_type(800,000) < W_rel(1,048,576)
    //   < edge_index(1,600,000) < x(12,800,000)
    int order[16];
    for (int i = 0; i < n_in; i++) order[i] = i;
    for (int a = 0; a < n_in; a++)
        for (int b = a + 1; b < n_in; b++)
            if (in_sizes[order[b]] < in_sizes[order[a]]) {
                int t = order[a]; order[a] = order[b]; order[b] = t;
            }
    const float* bias   = (const float*)d_in[order[0]];
    const float* W_self = (const float*)d_in[order[1]];
    const void*  et     = d_in[order[2]];
    const float* W_rel  = (const float*)d_in[order[3]];
    const void*  ei     = d_in[order[4]];
    const float* x      = (const float*)d_in[order[5]];

    int E = in_sizes[order[2]];
    int N = in_sizes[order[5]] / D;
    int R = in_sizes[order[3]] / (D * D);
    if (R < 1) R = 1;
    if (R > RMAX - 1) R = RMAX - 1;

    float* out = (float*)d_out;
    int total = N * D;

    k_detect<<<1, 256>>>((const int2*)ei, 256);
    k_zero_cnt<<<1, RMAX + 1>>>(R);
    k_hist<<<(E + 255) / 256, 256>>>(et, E, R);
    k_scan<<<1, 1>>>(R, N);
    k_scatter<<<(E + N + 255) / 256, 256>>>(ei, et, E, N, R);
    k_pad<<<((R + 1) * TM + 255) / 256, 256>>>(R);
    k_init<<<(total + 255) / 256, 256>>>(out, bias, total);

    // upper bound on padded tile count (blocks beyond g_ntiles self-exit)
    int tiles_max = (E + TM - 1) / TM + R + (N + TM - 1) / TM + 1;
    dim3 grid(tiles_max, D / TN);
    k_gemm<<<grid, 256>>>(x, W_rel, W_self, out, R);

    k_relu<<<(total + 255) / 256, 256>>>(out, total);
}

// round 4
// speedup vs baseline: 2.8547x; 2.8547x over previous
#include <cuda_runtime.h>
#include <cuda_bf16.h>
#include <stdint.h>

// RGCN layer: out = relu( scatter_add_dst( x[src] @ W_rel[edge_type] ) + x @ W_self + bias )
//
// R4: tensor-core gather-GEMM via bf16-split (A·B ≈ Ah·Bh + Ah·Bl + Al·Bh),
// mma.sync.m16n8k16, fp32 accumulate, red.global.add.v2 scatter epilogue.

#define D   256
#define TM  128
#define TN  64
#define RMAX 32
#define MAXSEG 1200000
#define MAXN 51200

__device__ int g_cnt[RMAX + 1];
__device__ int g_cur[RMAX + 1];
__device__ int g_off[RMAX + 2];
__device__ int g_srcbuf[MAXSEG];
__device__ int g_dstbuf[MAXSEG];
__device__ int g_ntiles;
__device__ int g_is64;

// bf16 hi/lo splits of x and W (W_self appended as relation R)
__device__ __nv_bfloat16 g_xh[MAXN * D];
__device__ __nv_bfloat16 g_xl[MAXN * D];
__device__ __nv_bfloat16 g_wh[(RMAX + 1) * D * D];
__device__ __nv_bfloat16 g_wl[(RMAX + 1) * D * D];

// ---------------------------------------------------------------------------
__global__ void k_detect(const int2* __restrict__ ei_pairs, int npairs) {
    __shared__ int zcnt;
    if (threadIdx.x == 0) zcnt = 0;
    __syncthreads();
    int i = threadIdx.x;
    if (i < npairs && ei_pairs[i].y == 0) atomicAdd(&zcnt, 1);
    __syncthreads();
    if (threadIdx.x == 0) g_is64 = (zcnt > npairs / 2) ? 1 : 0;
}

__global__ void k_zero_cnt(int R) {
    int i = threadIdx.x;
    if (i <= R) g_cnt[i] = 0;
}

__global__ void k_hist(const void* __restrict__ et, int E, int R) {
    __shared__ int h[RMAX + 1];
    if (threadIdx.x <= R) h[threadIdx.x] = 0;
    __syncthreads();
    int i = blockIdx.x * blockDim.x + threadIdx.x;
    if (i < E) {
        int r = g_is64 ? (int)((const long long*)et)[i] : ((const int*)et)[i];
        if (r < 0) r = 0;
        if (r >= R) r = R - 1;
        atomicAdd(&h[r], 1);
    }
    __syncthreads();
    if (threadIdx.x <= R && h[threadIdx.x]) atomicAdd(&g_cnt[threadIdx.x], h[threadIdx.x]);
}

__global__ void k_scan(int R, int N) {
    g_cnt[R] = N;
    int off = 0;
    for (int r = 0; r <= R; r++) {
        g_off[r] = off;
        g_cur[r] = off;
        off += ((g_cnt[r] + TM - 1) / TM) * TM;
    }
    g_off[R + 1] = off;
    g_ntiles = off / TM;
}

__global__ void k_scatter(const void* __restrict__ ei,
                          const void* __restrict__ et,
                          int E, int N, int R) {
    int i = blockIdx.x * blockDim.x + threadIdx.x;
    int is64 = g_is64;
    if (i < E) {
        int r, s, d;
        if (is64) {
            r = (int)((const long long*)et)[i];
            s = (int)((const long long*)ei)[i];
            d = (int)((const long long*)ei)[E + i];
        } else {
            r = ((const int*)et)[i];
            s = ((const int*)ei)[i];
            d = ((const int*)ei)[E + i];
        }
        if (r < 0) r = 0;
        if (r >= R) r = R - 1;
        if (s < 0 || s >= N) s = 0;
        if (d < 0 || d >= N) d = 0;
        int p = atomicAdd(&g_cur[r], 1);
        g_srcbuf[p] = s;
        g_dstbuf[p] = d;
    } else if (i < E + N) {
        int n = i - E;
        int p = g_off[R] + n;
        g_srcbuf[p] = n;
        g_dstbuf[p] = n;
    }
}

__global__ void k_pad(int R) {
    int i = blockIdx.x * blockDim.x + threadIdx.x;
    int r = i / TM;
    int j = i % TM;
    if (r > R) return;
    int idx = g_off[r] + g_cnt[r] + j;
    if (idx < g_off[r + 1]) {
        g_srcbuf[idx] = -1;
        g_dstbuf[idx] = 0;
    }
}

__global__ void k_split_x(const float* __restrict__ x, int total) {
    int i = blockIdx.x * blockDim.x + threadIdx.x;
    if (i < total) {
        float v = x[i];
        __nv_bfloat16 h = __float2bfloat16_rn(v);
        g_xh[i] = h;
        g_xl[i] = __float2bfloat16_rn(v - __bfloat162float(h));
    }
}

__global__ void k_split_w(const float* __restrict__ W_rel,
                          const float* __restrict__ W_self,
                          int R) {
    int i = blockIdx.x * blockDim.x + threadIdx.x;
    int total = (R + 1) * D * D;
    if (i < total) {
        float v = (i < R * D * D) ? W_rel[i] : W_self[i - R * D * D];
        __nv_bfloat16 h = __float2bfloat16_rn(v);
        g_wh[i] = h;
        g_wl[i] = __float2bfloat16_rn(v - __bfloat162float(h));
    }
}

__global__ void k_init(float* __restrict__ out, const float* __restrict__ bias, int total) {
    int i = blockIdx.x * blockDim.x + threadIdx.x;
    if (i < total) out[i] = bias[i & (D - 1)];
}

__global__ void k_relu(float* __restrict__ out, int total) {
    int i = blockIdx.x * blockDim.x + threadIdx.x;
    if (i < total) out[i] = fmaxf(out[i], 0.0f);
}

// ---------------------------------------------------------------------------
__device__ __forceinline__ uint32_t smem_u32(const void* p) {
    return (uint32_t)__cvta_generic_to_shared(p);
}

__device__ __forceinline__ void ldsm_x4(uint32_t* r, uint32_t addr) {
    asm volatile("ldmatrix.sync.aligned.m8n8.x4.shared.b16 {%0,%1,%2,%3}, [%4];"
                 : "=r"(r[0]), "=r"(r[1]), "=r"(r[2]), "=r"(r[3]) : "r"(addr));
}

__device__ __forceinline__ void ldsm_x4_t(uint32_t* r, uint32_t addr) {
    asm volatile("ldmatrix.sync.aligned.m8n8.x4.trans.shared.b16 {%0,%1,%2,%3}, [%4];"
                 : "=r"(r[0]), "=r"(r[1]), "=r"(r[2]), "=r"(r[3]) : "r"(addr));
}

__device__ __forceinline__ void mma_bf16(float* c, const uint32_t* a, const uint32_t* b) {
    asm volatile(
        "mma.sync.aligned.m16n8k16.row.col.f32.bf16.bf16.f32 "
        "{%0,%1,%2,%3}, {%4,%5,%6,%7}, {%8,%9}, {%0,%1,%2,%3};"
        : "+f"(c[0]), "+f"(c[1]), "+f"(c[2]), "+f"(c[3])
        : "r"(a[0]), "r"(a[1]), "r"(a[2]), "r"(a[3]), "r"(b[0]), "r"(b[1]));
}

// Tensor-core gather-GEMM with atomic scatter epilogue.
// grid: (tiles_max, D/TN); block: 256 threads = 8 warps; warp tile 16x64.
#define ASTRIDE 40   // bf16 elems per A smem row (TK=32 + 8 pad)
#define BSTRIDE 72   // bf16 elems per B smem row (TN=64 + 8 pad)

__global__ __launch_bounds__(256) void k_gemm_mma(float* __restrict__ out, int R) {
    int t = blockIdx.x;
    if (t >= g_ntiles) return;
    int row0 = t * TM;

    int rel = 0;
    while (g_off[rel + 1] <= row0) rel++;
    const __nv_bfloat16* __restrict__ Wh = g_wh + (size_t)rel * D * D;
    const __nv_bfloat16* __restrict__ Wl = g_wl + (size_t)rel * D * D;

    int n0 = blockIdx.y * TN;
    int tid = threadIdx.x;
    int warp = tid >> 5;
    int lane = tid & 31;
    int wm = warp * 16;      // warp's M offset within tile

    __shared__ __nv_bfloat16 sAh[TM * ASTRIDE];
    __shared__ __nv_bfloat16 sAl[TM * ASTRIDE];
    __shared__ __nv_bfloat16 sBh[32 * BSTRIDE];
    __shared__ __nv_bfloat16 sBl[32 * BSTRIDE];
    __shared__ int s_src[TM];
    __shared__ int s_dst[TM];

    if (tid < TM) {
        s_src[tid] = g_srcbuf[row0 + tid];
        s_dst[tid] = g_dstbuf[row0 + tid];
    }
    __syncthreads();

    float acc[8][4];
    #pragma unroll
    for (int g = 0; g < 8; g++)
        #pragma unroll
        for (int j = 0; j < 4; j++) acc[g][j] = 0.0f;

    const uint4 zero4 = make_uint4(0, 0, 0, 0);

    // ldmatrix lane addressing (constant across k-chunks)
    int a_row = wm + (lane & 15);
    int a_colsel = (lane >> 4) << 3;
    int b_mat = lane >> 3;
    int b_rowoff = (lane & 7) + (b_mat & 1) * 8;
    int b_coloff = (b_mat >> 1) << 3;

    #pragma unroll 1
    for (int kt = 0; kt < 8; kt++) {       // K chunks of 32
        int k0 = kt * 32;
        // --- A fill: 128x32 hi+lo, uint4 (8 bf16) per op, 2+2 per thread
        #pragma unroll
        for (int i = 0; i < 2; i++) {
            int idx = tid + i * 256;       // 0..511
            int r = idx >> 2;
            int kg = (idx & 3) << 3;
            int sr = s_src[r];
            uint4* dh = (uint4*)&sAh[r * ASTRIDE + kg];
            uint4* dl = (uint4*)&sAl[r * ASTRIDE + kg];
            if (sr < 0) {
                *dh = zero4; *dl = zero4;
            } else {
                size_t gi = (size_t)sr * D + k0 + kg;
                *dh = *(const uint4*)&g_xh[gi];
                *dl = *(const uint4*)&g_xl[gi];
            }
        }
        // --- B fill: 32x64 hi+lo, 1+1 uint4 per thread
        {
            int r = tid >> 3;
            int ng = (tid & 7) << 3;
            size_t gi = (size_t)(k0 + r) * D + n0 + ng;
            *(uint4*)&sBh[r * BSTRIDE + ng] = *(const uint4*)&Wh[gi];
            *(uint4*)&sBl[r * BSTRIDE + ng] = *(const uint4*)&Wl[gi];
        }
        __syncthreads();

        #pragma unroll
        for (int ks = 0; ks < 32; ks += 16) {
            uint32_t ah[4], al[4];
            uint32_t a_addr_h = smem_u32(&sAh[a_row * ASTRIDE + ks + a_colsel]);
            uint32_t a_addr_l = smem_u32(&sAl[a_row * ASTRIDE + ks + a_colsel]);
            ldsm_x4(ah, a_addr_h);
            ldsm_x4(al, a_addr_l);

            #pragma unroll
            for (int p = 0; p < 4; p++) {  // 16-col pairs of n-groups
                uint32_t bh[4], bl[4];
                int bc = p * 16 + b_coloff;
                ldsm_x4_t(bh, smem_u32(&sBh[(ks + b_rowoff) * BSTRIDE + bc]));
                ldsm_x4_t(bl, smem_u32(&sBl[(ks + b_rowoff) * BSTRIDE + bc]));
                // ng = 2p   -> regs {0,1};  ng = 2p+1 -> regs {2,3}
                mma_bf16(acc[2 * p],     ah, &bh[0]);
                mma_bf16(acc[2 * p],     ah, &bl[0]);
                mma_bf16(acc[2 * p],     al, &bh[0]);
                mma_bf16(acc[2 * p + 1], ah, &bh[2]);
                mma_bf16(acc[2 * p + 1], ah, &bl[2]);
                mma_bf16(acc[2 * p + 1], al, &bh[2]);
            }
        }
        __syncthreads();
    }

    // --- epilogue: red.global.add.v2 into out[dst]
    int lr0 = wm + (lane >> 2);
    int lr1 = lr0 + 8;
    int s0 = s_src[lr0], s1 = s_src[lr1];
    long long d0 = (long long)s_dst[lr0] * D;
    long long d1 = (long long)s_dst[lr1] * D;
    int colb = n0 + ((lane & 3) << 1);
    #pragma unroll
    for (int g = 0; g < 8; g++) {
        int col = colb + g * 8;
        if (s0 >= 0) {
            float* p = out + d0 + col;
            asm volatile("red.global.add.v2.f32 [%0], {%1, %2};"
                         :: "l"(p), "f"(acc[g][0]), "f"(acc[g][1]) : "memory");
        }
        if (s1 >= 0) {
            float* p = out + d1 + col;
            asm volatile("red.global.add.v2.f32 [%0], {%1, %2};"
                         :: "l"(p), "f"(acc[g][2]), "f"(acc[g][3]) : "memory");
        }
    }
}

// ---------------------------------------------------------------------------
extern "C" void kernel_launch(void* const* d_in, const int* in_sizes, int n_in,
                              void* d_out, int out_size) {
    // Bind inputs by element count (all six pairwise distinct):
    //   bias(256) < W_self(65,536) < edge_type(800k) < W_rel(1,048,576)
    //   < edge_index(1.6M) < x(12.8M)
    int order[16];
    for (int i = 0; i < n_in; i++) order[i] = i;
    for (int a = 0; a < n_in; a++)
        for (int b = a + 1; b < n_in; b++)
            if (in_sizes[order[b]] < in_sizes[order[a]]) {
                int t = order[a]; order[a] = order[b]; order[b] = t;
            }
    const float* bias   = (const float*)d_in[order[0]];
    const float* W_self = (const float*)d_in[order[1]];
    const void*  et     = d_in[order[2]];
    const float* W_rel  = (const float*)d_in[order[3]];
    const void*  ei     = d_in[order[4]];
    const float* x      = (const float*)d_in[order[5]];

    int E = in_sizes[order[2]];
    int N = in_sizes[order[5]] / D;
    int R = in_sizes[order[3]] / (D * D);
    if (R < 1) R = 1;
    if (R > RMAX - 1) R = RMAX - 1;
    if (N > MAXN) N = MAXN;

    float* out = (float*)d_out;
    int total = N * D;

    k_detect<<<1, 256>>>((const int2*)ei, 256);
    k_zero_cnt<<<1, RMAX + 1>>>(R);
    k_hist<<<(E + 255) / 256, 256>>>(et, E, R);
    k_scan<<<1, 1>>>(R, N);
    k_scatter<<<(E + N + 255) / 256, 256>>>(ei, et, E, N, R);
    k_pad<<<((R + 1) * TM + 255) / 256, 256>>>(R);
    k_split_x<<<(total + 255) / 256, 256>>>(x, total);
    k_split_w<<<((R + 1) * D * D + 255) / 256, 256>>>(W_rel, W_self, R);
    k_init<<<(total + 255) / 256, 256>>>(out, bias, total);

    int tiles_max = (E + TM - 1) / TM + R + (N + TM - 1) / TM + 1;
    dim3 grid(tiles_max, D / TN);
    k_gemm_mma<<<grid, 256>>>(out, R);

    k_relu<<<(total + 255) / 256, 256>>>(out, total);
}